// round 14
// baseline (speedup 1.0000x reference)
#include <cuda_runtime.h>
#include <cuda_fp16.h>
#include <cstdint>

#define NB   32
#define CIN  128
#define COUT 128
#define LEN  4096
#define KSZ  3
#define LT   128                // l-tile (M) per CTA
#define XSTRIDE 136             // fp16 per X row = 272B (ldsm-friendly)
#define STW 132                 // f32 staging row stride (words), 16B-aligned rows
#define WOFFB(buf) ((buf) * 16384)
#define STOFF 32768             // f32 staging tile [64][STW] (reused twice)
#define XOFF  66560             // X fp16 tile [130][XSTRIDE]
#define SMEM_TOTAL (XOFF + 130 * XSTRIDE * 2)    // 101920 bytes

// Prepped W images: [b][kk][ic] -> 64 i-rows x 128 o fp16 (swizzle at cp.async)
__device__ __align__(16) __half g_Wimg[NB * KSZ * 2 * 8192];   // 3.1 MB
__device__ float g_bias2[NB * COUT];

// ---------------------------------------------------------------------------
// helpers (baseline PTX, compiles for compute_103)
// ---------------------------------------------------------------------------
__device__ __forceinline__ uint32_t smem_u32(const void* p) {
    return (uint32_t)__cvta_generic_to_shared(p);
}
__device__ __forceinline__ void cp16(uint32_t saddr, const void* g) {
    asm volatile("cp.async.cg.shared.global [%0], [%1], 16;\n" :: "r"(saddr), "l"(g));
}
#define CP_COMMIT() asm volatile("cp.async.commit_group;\n" ::: "memory")
#define CP_WAIT0()  asm volatile("cp.async.wait_group 0;\n" ::: "memory")

__device__ __forceinline__ void ldsm4(uint32_t* d, uint32_t a) {
    asm volatile("ldmatrix.sync.aligned.m8n8.x4.shared.b16 {%0,%1,%2,%3}, [%4];"
                 : "=r"(d[0]), "=r"(d[1]), "=r"(d[2]), "=r"(d[3]) : "r"(a));
}
__device__ __forceinline__ void ldsm4t(uint32_t* d, uint32_t a) {
    asm volatile("ldmatrix.sync.aligned.m8n8.x4.trans.shared.b16 {%0,%1,%2,%3}, [%4];"
                 : "=r"(d[0]), "=r"(d[1]), "=r"(d[2]), "=r"(d[3]) : "r"(a));
}
__device__ __forceinline__ void mma16816(float* c, const uint32_t* a, const uint32_t* b) {
    asm volatile("mma.sync.aligned.m16n8k16.row.col.f32.f16.f16.f32 "
                 "{%0,%1,%2,%3}, {%4,%5,%6,%7}, {%8,%9}, {%0,%1,%2,%3};"
                 : "+f"(c[0]), "+f"(c[1]), "+f"(c[2]), "+f"(c[3])
                 : "r"(a[0]), "r"(a[1]), "r"(a[2]), "r"(a[3]), "r"(b[0]), "r"(b[1]));
}

// ---------------------------------------------------------------------------
// Kernel 1: hypernetwork weights -> fp16 W images, coalesced read + staged write.
// ---------------------------------------------------------------------------
__global__ void geps_prep_kernel(const float* __restrict__ codes,
                                 const float* __restrict__ weight,
                                 const float* __restrict__ A,
                                 const float* __restrict__ Bm,
                                 const float* __restrict__ bias,
                                 const float* __restrict__ bctx) {
    __shared__ __half s2[3 * 128 * 18];    // 13.5 KB
    const int b  = blockIdx.x;
    const int o0 = blockIdx.y * 16;
    const int tid = threadIdx.x;

    const float c00 = codes[b * 4 + 0];
    const float c01 = codes[b * 4 + 1];
    const float c10 = codes[b * 4 + 2];
    const float c11 = codes[b * 4 + 3];

#pragma unroll
    for (int r = 0; r < 8; ++r) {
        const int p  = r * 256 + tid;      // 2048 (o_l, i) pairs
        const int i  = p & 127;
        const int ol = p >> 7;
        const int o  = o0 + ol;
        const float* wp = weight + (size_t)(o * 128 + i) * 3;
        const float wk0 = wp[0], wk1 = wp[1], wk2 = wp[2];
#pragma unroll
        for (int kk = 0; kk < KSZ; ++kk) {
            const float a0 = A[i * 6 + kk];
            const float a1 = A[i * 6 + 3 + kk];
            const float g0 = a0 * c00 + a1 * c10;
            const float g1 = a0 * c01 + a1 * c11;
            const float wkk = (kk == 0) ? wk0 : (kk == 1 ? wk1 : wk2);
            const float cw = wkk + g0 * Bm[o * 6 + kk] + g1 * Bm[o * 6 + 3 + kk];
            s2[(kk * 128 + i) * 18 + ol] = __float2half(cw);
        }
    }
    __syncthreads();

#pragma unroll
    for (int r = 0; r < 12; ++r) {
        const int w  = r * 256 + tid;      // 3072 u32 (2 o each)
        const int o2 = w & 7;
        const int i  = (w >> 3) & 127;
        const int kk = w >> 10;
        const int ic = i >> 6, il = i & 63;
        const uint32_t v = *(const uint32_t*)&s2[(kk * 128 + i) * 18 + 2 * o2];
        ((uint32_t*)g_Wimg)[(size_t)((b * 3 + kk) * 2 + ic) * 4096
                            + il * 64 + (o0 >> 1) + o2] = v;
    }

    if (blockIdx.y == 0 && tid < COUT) {
        const int o = tid;
        g_bias2[b * COUT + o] = bias[o] + c00 * bctx[o] + c11 * bctx[COUT + o];
    }
}

// ---------------------------------------------------------------------------
// Kernel 2: HMMA fp16 implicit-GEMM conv. CTA 128l x 128o, 8 warps (2m x 4n),
// warp tile 64x32. ks-staggered mainloop; conflict-free fill transpose.
// ---------------------------------------------------------------------------
__global__ __launch_bounds__(256, 2)
void geps_mma_kernel(const float* __restrict__ x, float* __restrict__ out) {
    extern __shared__ char smem[];
    const int tid = threadIdx.x;
    const int wid = tid >> 5;
    const int lane = tid & 31;
    const int b  = blockIdx.y;
    const int l0 = blockIdx.x * LT;
    const float* xb = x + (size_t)b * CIN * LEN;

    float*  sT  = (float*)(smem + STOFF);            // staging [64][STW] f32
    float*  sC  = (float*)smem;                      // epilogue overlay [128][131]
    __half* sXh = (__half*)(smem + XOFF);            // [130][XSTRIDE] fp16
    const uint32_t sbase = smem_u32(smem);

    // ---- W chunk loader: 16KB, XOR-swizzled 16B chunks
    auto issue_w = [&](int step, int buf) {
        const int kk = step % 3, ic = step / 3;
        const __half* src = (const __half*)g_Wimg
                          + (size_t)((b * 3 + kk) * 2 + ic) * 8192;
        const uint32_t dbase = sbase + WOFFB(buf);
#pragma unroll
        for (int t = 0; t < 4; ++t) {
            const int v = tid + t * 256;
            const int row = v >> 4, c = v & 15;
            cp16(dbase + row * 256 + ((c ^ (row & 7)) << 4), src + v * 8);
        }
        CP_COMMIT();
    };

    issue_w(0, 0);    // overlap W0 with X fill

    // halo rows: row 0 = l0-1 (wrap), row 129 = l0+128 (wrap)
    {
        const int i = tid & 127;
        const int side = tid >> 7;
        const int gl = side ? ((l0 + LT) & (LEN - 1)) : ((l0 + LEN - 1) & (LEN - 1));
        const int row = side ? (LT + 1) : 0;
        sXh[row * XSTRIDE + i] = __float2half(xb[(size_t)i * LEN + gl]);
    }

    // ---- X fill in two i-halves through the f32 staging tile
#pragma unroll
    for (int ih = 0; ih < 2; ++ih) {
        const int i0h = 64 * ih;
        __syncthreads();      // sT free (prev half consumed / first entry)
        // stage A: coalesced LDG.128 -> conflict-free STS.128, sT[i][l]
#pragma unroll
        for (int r = 0; r < 8; ++r) {
            const int idx = r * 256 + tid;          // 2048 float4
            const int c = idx & 31;                 // l4-col 0..31
            const int i = idx >> 5;                 // 0..63
            const float4 v = *(const float4*)(xb + (size_t)(i0h + i) * LEN + l0 + 4 * c);
            *(float4*)(sT + i * STW + 4 * c) = v;
        }
        __syncthreads();
        // stage B: transpose sT -> sXh[l+1][i0h+..]; lane map (a=l-low, c=i-grp)
        // with c-rotated l-blocks => conflict-free LDS.32 reads AND uint2 stores
        {
            const int a = tid & 7;                  // l low bits
            const int c = (tid >> 3) & 3;           // i-group low
            const int w = tid >> 5;                 // warp id
#pragma unroll
            for (int it = 0; it < 8; ++it) {
                const int lb0 = (it & 1) * 8 + w;             // 0..15
                const int cb  = it >> 1;                      // 0..3
                const int lrow = a + 8 * ((lb0 + c) & 15);    // 0..127
                const int ig = cb * 4 + c;                    // 0..15
                const float a0 = sT[(4 * ig + 0) * STW + lrow];
                const float a1 = sT[(4 * ig + 1) * STW + lrow];
                const float a2 = sT[(4 * ig + 2) * STW + lrow];
                const float a3 = sT[(4 * ig + 3) * STW + lrow];
                union { uint2 u; __half2 h[2]; } pk;
                pk.h[0] = __floats2half2_rn(a0, a1);
                pk.h[1] = __floats2half2_rn(a2, a3);
                *(uint2*)(&sXh[(lrow + 1) * XSTRIDE + i0h + 4 * ig]) = pk.u;
            }
        }
    }

    // ---- lane-derived ldmatrix address components
    const int g = lane >> 3, r = lane & 7;
    const int arow = ((g & 1) << 3) + r;
    const int achk = g >> 1;
    const int wm = wid & 1, wn = wid >> 1;
    const int m0 = 64 * wm, n0 = 32 * wn;

    float acc[4][4][4];
#pragma unroll
    for (int mt = 0; mt < 4; ++mt)
#pragma unroll
        for (int nt = 0; nt < 4; ++nt)
#pragma unroll
            for (int q = 0; q < 4; ++q) acc[mt][nt][q] = 0.f;

    const uint32_t xhib = sbase + XOFF;

    for (int step = 0; step < 6; ++step) {
        const int buf = step & 1;
        CP_WAIT0();
        __syncthreads();                 // W(step) + X visible
        if (step + 1 < 6) issue_w(step + 1, buf ^ 1);

        const int kk = step % 3;
        const int ic = step / 3;
        const uint32_t wb_ = sbase + WOFFB(buf);

#pragma unroll
        for (int ksi = 0; ksi < 4; ++ksi) {
            const int ks = (ksi + wid) & 3;     // per-warp stagger: mix pipes
            uint32_t ah[4][4], bw[8];
#pragma unroll
            for (int mt = 0; mt < 4; ++mt) {
                const uint32_t off =
                    (uint32_t)((kk + m0 + 16 * mt + arow) * 272 +
                               (8 * ic + 2 * ks + achk) * 16);
                ldsm4(ah[mt], xhib + off);
            }
            const int rowB = 16 * ks + arow;
#pragma unroll
            for (int h = 0; h < 2; ++h) {
                const int cB = 4 * wn + 2 * h + achk;
                const uint32_t off =
                    (uint32_t)(rowB * 256 + ((cB ^ (rowB & 7)) << 4));
                ldsm4t(&bw[4 * h], wb_ + off);
            }
#pragma unroll
            for (int mt = 0; mt < 4; ++mt)
#pragma unroll
                for (int nt = 0; nt < 4; ++nt)
                    mma16816(acc[mt][nt], ah[mt], &bw[2 * nt]);
        }
    }

    // ---- epilogue: stage C[l][o] through smem (stride 131), coalesced stores
    __syncthreads();
    {
        const int gr = lane >> 2, cid = lane & 3;
#pragma unroll
        for (int mt = 0; mt < 4; ++mt)
#pragma unroll
            for (int nt = 0; nt < 4; ++nt) {
                const int m = m0 + 16 * mt + gr;
                const int n = n0 + 8 * nt + 2 * cid;
                sC[m * 131 + n]           = acc[mt][nt][0];
                sC[m * 131 + n + 1]       = acc[mt][nt][1];
                sC[(m + 8) * 131 + n]     = acc[mt][nt][2];
                sC[(m + 8) * 131 + n + 1] = acc[mt][nt][3];
            }
    }
    __syncthreads();
    {
        const float* bb = g_bias2 + b * COUT;
#pragma unroll
        for (int jj = 0; jj < 16; ++jj) {
            const int o = wid * 16 + jj;
            const float bv = bb[o];
            float* op = out + ((size_t)b * COUT + o) * LEN + l0;
#pragma unroll
            for (int qh = 0; qh < 4; ++qh) {
                const int l = 32 * qh + lane;
                op[l] = sC[l * 131 + o] + bv;
            }
        }
    }
}

extern "C" void kernel_launch(void* const* d_in, const int* in_sizes, int n_in,
                              void* d_out, int out_size) {
    const float* input  = (const float*)d_in[0];   // (32,128,4096)
    const float* codes  = (const float*)d_in[1];   // (32,2,2)
    const float* weight = (const float*)d_in[2];   // (128,128,3)
    const float* A      = (const float*)d_in[3];   // (128,2,3)
    const float* Bm     = (const float*)d_in[4];   // (128,2,3)
    const float* bias   = (const float*)d_in[5];   // (128,)
    const float* bctx   = (const float*)d_in[6];   // (2,128)
    float* out = (float*)d_out;                    // (32,128,4096)

    cudaFuncSetAttribute(geps_mma_kernel,
                         cudaFuncAttributeMaxDynamicSharedMemorySize, SMEM_TOTAL);

    dim3 pgrid(NB, 8);
    geps_prep_kernel<<<pgrid, 256>>>(codes, weight, A, Bm, bias, bctx);

    dim3 cgrid(LEN / LT, NB);
    geps_mma_kernel<<<cgrid, 256, SMEM_TOTAL>>>(input, out);
}

// round 15
// speedup vs baseline: 1.1100x; 1.1100x over previous
#include <cuda_runtime.h>
#include <cuda_fp16.h>
#include <cstdint>

#define NB   32
#define CIN  128
#define COUT 128
#define LEN  4096
#define KSZ  3
#define LT   128                // l-tile (M) per CTA
#define XSTRIDE 136             // fp16 per X row = 272B (ldsm-friendly)
#define STW 132                 // f32 staging row stride (words), 16B-aligned rows
#define WOFFB(buf) ((buf) * 16384)
#define STOFF 32768             // f32 staging tile [64][STW] (reused twice)
#define XOFF  66560             // X fp16 tile [130][XSTRIDE]
#define SMEM_TOTAL (XOFF + 130 * XSTRIDE * 2)    // 101920 bytes

// Prepped W images: [b][kk][ic] -> 64 i-rows x 128 o fp16 (swizzle at cp.async)
__device__ __align__(16) __half g_Wimg[NB * KSZ * 2 * 8192];   // 3.1 MB
__device__ float g_bias2[NB * COUT];

// ---------------------------------------------------------------------------
// helpers (baseline PTX, compiles for compute_103)
// ---------------------------------------------------------------------------
__device__ __forceinline__ uint32_t smem_u32(const void* p) {
    return (uint32_t)__cvta_generic_to_shared(p);
}
__device__ __forceinline__ void cp16(uint32_t saddr, const void* g) {
    asm volatile("cp.async.cg.shared.global [%0], [%1], 16;\n" :: "r"(saddr), "l"(g));
}
#define CP_COMMIT() asm volatile("cp.async.commit_group;\n" ::: "memory")
#define CP_WAIT0()  asm volatile("cp.async.wait_group 0;\n" ::: "memory")
#define CP_WAIT1()  asm volatile("cp.async.wait_group 1;\n" ::: "memory")

__device__ __forceinline__ void ldsm4(uint32_t* d, uint32_t a) {
    asm volatile("ldmatrix.sync.aligned.m8n8.x4.shared.b16 {%0,%1,%2,%3}, [%4];"
                 : "=r"(d[0]), "=r"(d[1]), "=r"(d[2]), "=r"(d[3]) : "r"(a));
}
__device__ __forceinline__ void ldsm4t(uint32_t* d, uint32_t a) {
    asm volatile("ldmatrix.sync.aligned.m8n8.x4.trans.shared.b16 {%0,%1,%2,%3}, [%4];"
                 : "=r"(d[0]), "=r"(d[1]), "=r"(d[2]), "=r"(d[3]) : "r"(a));
}
__device__ __forceinline__ void mma16816(float* c, const uint32_t* a, const uint32_t* b) {
    asm volatile("mma.sync.aligned.m16n8k16.row.col.f32.f16.f16.f32 "
                 "{%0,%1,%2,%3}, {%4,%5,%6,%7}, {%8,%9}, {%0,%1,%2,%3};"
                 : "+f"(c[0]), "+f"(c[1]), "+f"(c[2]), "+f"(c[3])
                 : "r"(a[0]), "r"(a[1]), "r"(a[2]), "r"(a[3]), "r"(b[0]), "r"(b[1]));
}

// ---------------------------------------------------------------------------
// Kernel 1: hypernetwork weights -> fp16 W images, coalesced read + staged write.
// ---------------------------------------------------------------------------
__global__ void geps_prep_kernel(const float* __restrict__ codes,
                                 const float* __restrict__ weight,
                                 const float* __restrict__ A,
                                 const float* __restrict__ Bm,
                                 const float* __restrict__ bias,
                                 const float* __restrict__ bctx) {
    __shared__ __half s2[3 * 128 * 18];    // 13.5 KB
    const int b  = blockIdx.x;
    const int o0 = blockIdx.y * 16;
    const int tid = threadIdx.x;

    const float c00 = codes[b * 4 + 0];
    const float c01 = codes[b * 4 + 1];
    const float c10 = codes[b * 4 + 2];
    const float c11 = codes[b * 4 + 3];

#pragma unroll
    for (int r = 0; r < 8; ++r) {
        const int p  = r * 256 + tid;      // 2048 (o_l, i) pairs
        const int i  = p & 127;
        const int ol = p >> 7;
        const int o  = o0 + ol;
        const float* wp = weight + (size_t)(o * 128 + i) * 3;
        const float wk0 = wp[0], wk1 = wp[1], wk2 = wp[2];
#pragma unroll
        for (int kk = 0; kk < KSZ; ++kk) {
            const float a0 = A[i * 6 + kk];
            const float a1 = A[i * 6 + 3 + kk];
            const float g0 = a0 * c00 + a1 * c10;
            const float g1 = a0 * c01 + a1 * c11;
            const float wkk = (kk == 0) ? wk0 : (kk == 1 ? wk1 : wk2);
            const float cw = wkk + g0 * Bm[o * 6 + kk] + g1 * Bm[o * 6 + 3 + kk];
            s2[(kk * 128 + i) * 18 + ol] = __float2half(cw);
        }
    }
    __syncthreads();

#pragma unroll
    for (int r = 0; r < 12; ++r) {
        const int w  = r * 256 + tid;      // 3072 u32 (2 o each)
        const int o2 = w & 7;
        const int i  = (w >> 3) & 127;
        const int kk = w >> 10;
        const int ic = i >> 6, il = i & 63;
        const uint32_t v = *(const uint32_t*)&s2[(kk * 128 + i) * 18 + 2 * o2];
        ((uint32_t*)g_Wimg)[(size_t)((b * 3 + kk) * 2 + ic) * 4096
                            + il * 64 + (o0 >> 1) + o2] = v;
    }

    if (blockIdx.y == 0 && tid < COUT) {
        const int o = tid;
        g_bias2[b * COUT + o] = bias[o] + c00 * bctx[o] + c11 * bctx[COUT + o];
    }
}

// ---------------------------------------------------------------------------
// Kernel 2: HMMA fp16 implicit-GEMM conv. CTA 128l x 128o, 8 warps (2m x 4n),
// warp tile 64x32. cp.async X fill, second i-half pipelined behind compute.
// ---------------------------------------------------------------------------
__global__ __launch_bounds__(256, 2)
void geps_mma_kernel(const float* __restrict__ x, float* __restrict__ out) {
    extern __shared__ char smem[];
    const int tid = threadIdx.x;
    const int wid = tid >> 5;
    const int lane = tid & 31;
    const int b  = blockIdx.y;
    const int l0 = blockIdx.x * LT;
    const float* xb = x + (size_t)b * CIN * LEN;

    float*  sT  = (float*)(smem + STOFF);            // staging [64][STW] f32
    float*  sC  = (float*)smem;                      // epilogue overlay [128][131]
    __half* sXh = (__half*)(smem + XOFF);            // [130][XSTRIDE] fp16
    const uint32_t sbase = smem_u32(smem);

    // ---- W chunk loader: 16KB, XOR-swizzled 16B chunks (one commit group)
    auto issue_w = [&](int step, int buf) {
        const int kk = step % 3, ic = step / 3;
        const __half* src = (const __half*)g_Wimg
                          + (size_t)((b * 3 + kk) * 2 + ic) * 8192;
        const uint32_t dbase = sbase + WOFFB(buf);
#pragma unroll
        for (int t = 0; t < 4; ++t) {
            const int v = tid + t * 256;
            const int row = v >> 4, c = v & 15;
            cp16(dbase + row * 256 + ((c ^ (row & 7)) << 4), src + v * 8);
        }
        CP_COMMIT();
    };

    // ---- X stage A via cp.async: x[i0h+i][l0..l0+127] -> sT[i][:] (one group)
    auto issue_a = [&](int ih) {
        const int i0h = 64 * ih;
#pragma unroll
        for (int r = 0; r < 8; ++r) {
            const int idx = r * 256 + tid;          // 2048 x 16B
            const int c = idx & 31;
            const int i = idx >> 5;
            cp16(sbase + STOFF + (uint32_t)(i * STW + 4 * c) * 4,
                 xb + (size_t)(i0h + i) * LEN + l0 + 4 * c);
        }
        CP_COMMIT();
    };

    // ---- X stage B: transpose sT -> sXh[l+1][i0h+..]; conflict-free both ways
    auto stage_b = [&](int ih) {
        const int i0h = 64 * ih;
        const int a = tid & 7;                      // l low bits
        const int c = (tid >> 3) & 3;               // i-group low
        const int w = tid >> 5;                     // warp id
#pragma unroll
        for (int it = 0; it < 8; ++it) {
            const int lb0 = (it & 1) * 8 + w;             // 0..15
            const int cb  = it >> 1;                      // 0..3
            const int lrow = a + 8 * ((lb0 + c) & 15);    // 0..127
            const int ig = cb * 4 + c;                    // 0..15
            const float a0 = sT[(4 * ig + 0) * STW + lrow];
            const float a1 = sT[(4 * ig + 1) * STW + lrow];
            const float a2 = sT[(4 * ig + 2) * STW + lrow];
            const float a3 = sT[(4 * ig + 3) * STW + lrow];
            union { uint2 u; __half2 h[2]; } pk;
            pk.h[0] = __floats2half2_rn(a0, a1);
            pk.h[1] = __floats2half2_rn(a2, a3);
            *(uint2*)(&sXh[(lrow + 1) * XSTRIDE + i0h + 4 * ig]) = pk.u;
        }
    };

    // ---- prologue: A0 group, W0 group, halo; transpose lower half
    issue_a(0);                       // group: A0
    issue_w(0, 0);                    // group: W0
    {   // halo rows: row 0 = l0-1 (wrap), row 129 = l0+128 (wrap)
        const int i = tid & 127;
        const int side = tid >> 7;
        const int gl = side ? ((l0 + LT) & (LEN - 1)) : ((l0 + LEN - 1) & (LEN - 1));
        const int row = side ? (LT + 1) : 0;
        sXh[row * XSTRIDE + i] = __float2half(xb[(size_t)i * LEN + gl]);
    }
    CP_WAIT1();                       // A0 done (W0 may still fly)
    __syncthreads();
    stage_b(0);                       // X lower half ready after next barrier

    // ---- lane-derived ldmatrix address components
    const int g = lane >> 3, r = lane & 7;
    const int arow = ((g & 1) << 3) + r;
    const int achk = g >> 1;
    const int wm = wid & 1, wn = wid >> 1;
    const int m0 = 64 * wm, n0 = 32 * wn;

    float acc[4][4][4];
#pragma unroll
    for (int mt = 0; mt < 4; ++mt)
#pragma unroll
        for (int nt = 0; nt < 4; ++nt)
#pragma unroll
            for (int q = 0; q < 4; ++q) acc[mt][nt][q] = 0.f;

    const uint32_t xhib = sbase + XOFF;

    for (int step = 0; step < 6; ++step) {
        const int buf = step & 1;
        // step 1: W1 is all-but-newest (A1 newest) -> wait_group 1 suffices
        if (step == 1) CP_WAIT1(); else CP_WAIT0();
        __syncthreads();                 // W(step) (+A1 at step>=2) visible
        if (step == 0) { issue_w(1, 1); issue_a(1); }
        else if (step + 1 < 6) issue_w(step + 1, (step + 1) & 1);
        if (step == 2) stage_b(1);       // upper half; consumed from step 3

        const int kk = step % 3;
        const int ic = step / 3;
        const uint32_t wb_ = sbase + WOFFB(buf);

#pragma unroll
        for (int ks = 0; ks < 4; ++ks) {
            uint32_t ah[4][4], bw[8];
#pragma unroll
            for (int mt = 0; mt < 4; ++mt) {
                const uint32_t off =
                    (uint32_t)((kk + m0 + 16 * mt + arow) * 272 +
                               (8 * ic + 2 * ks + achk) * 16);
                ldsm4(ah[mt], xhib + off);
            }
            const int rowB = 16 * ks + arow;
#pragma unroll
            for (int h = 0; h < 2; ++h) {
                const int cB = 4 * wn + 2 * h + achk;
                const uint32_t off =
                    (uint32_t)(rowB * 256 + ((cB ^ (rowB & 7)) << 4));
                ldsm4t(&bw[4 * h], wb_ + off);
            }
#pragma unroll
            for (int mt = 0; mt < 4; ++mt)
#pragma unroll
                for (int nt = 0; nt < 4; ++nt)
                    mma16816(acc[mt][nt], ah[mt], &bw[2 * nt]);
        }
    }

    // ---- epilogue: stage C[l][o] through smem (stride 131), coalesced stores
    __syncthreads();
    {
        const int gr = lane >> 2, cid = lane & 3;
#pragma unroll
        for (int mt = 0; mt < 4; ++mt)
#pragma unroll
            for (int nt = 0; nt < 4; ++nt) {
                const int m = m0 + 16 * mt + gr;
                const int n = n0 + 8 * nt + 2 * cid;
                sC[m * 131 + n]           = acc[mt][nt][0];
                sC[m * 131 + n + 1]       = acc[mt][nt][1];
                sC[(m + 8) * 131 + n]     = acc[mt][nt][2];
                sC[(m + 8) * 131 + n + 1] = acc[mt][nt][3];
            }
    }
    __syncthreads();
    {
        const float* bb = g_bias2 + b * COUT;
#pragma unroll
        for (int jj = 0; jj < 16; ++jj) {
            const int o = wid * 16 + jj;
            const float bv = bb[o];
            float* op = out + ((size_t)b * COUT + o) * LEN + l0;
#pragma unroll
            for (int qh = 0; qh < 4; ++qh) {
                const int l = 32 * qh + lane;
                op[l] = sC[l * 131 + o] + bv;
            }
        }
    }
}

extern "C" void kernel_launch(void* const* d_in, const int* in_sizes, int n_in,
                              void* d_out, int out_size) {
    const float* input  = (const float*)d_in[0];   // (32,128,4096)
    const float* codes  = (const float*)d_in[1];   // (32,2,2)
    const float* weight = (const float*)d_in[2];   // (128,128,3)
    const float* A      = (const float*)d_in[3];   // (128,2,3)
    const float* Bm     = (const float*)d_in[4];   // (128,2,3)
    const float* bias   = (const float*)d_in[5];   // (128,)
    const float* bctx   = (const float*)d_in[6];   // (2,128)
    float* out = (float*)d_out;                    // (32,128,4096)

    cudaFuncSetAttribute(geps_mma_kernel,
                         cudaFuncAttributeMaxDynamicSharedMemorySize, SMEM_TOTAL);

    dim3 pgrid(NB, 8);
    geps_prep_kernel<<<pgrid, 256>>>(codes, weight, A, Bm, bias, bctx);

    dim3 cgrid(LEN / LT, NB);
    geps_mma_kernel<<<cgrid, 256, SMEM_TOTAL>>>(input, out);
}